// round 1
// baseline (speedup 1.0000x reference)
#include <cuda_runtime.h>
#include <math.h>
#include <stdint.h>

// ---------------------------------------------------------------------------
// Problem constants: B=4, T=1024, C=1024, H=16, Dh=64, D_FF=4096, WINDOW=256
// tokens M = 4096
// ---------------------------------------------------------------------------
#define TOKENS 4096
#define CDIM   1024
#define FFDIM  4096
#define NHEAD  16
#define DH     64
#define WIN    256

// Scratch (device globals: allocation-free rule)
__device__ float g_qkv[TOKENS * 3 * CDIM];   // 48M floats? no: 4096*3072
__device__ float g_ctx[TOKENS * CDIM];
__device__ float g_y[TOKENS * CDIM];
__device__ float g_x1[TOKENS * CDIM];
__device__ float g_h[TOKENS * FFDIM];

// ---------------------------------------------------------------------------
// GEMM: C[m,n] = sum_k A[m,k] * B[n,k] + bias[n]  (+resid)  (+gelu)
// A: [M,K] row-major, B: [N,K] row-major (both K-major -> symmetric loads)
// 128x128 tile, BK=16, 256 threads, 8x8 per thread (4+4 split in each dim)
// ---------------------------------------------------------------------------
#define BM 128
#define BN 128
#define BK 16
#define TPAD 132  // padded row stride for transposed smem tiles

__device__ __forceinline__ float gelu_exact(float v) {
    return 0.5f * v * (1.0f + erff(v * 0.70710678118654752f));
}

template <bool GELU, bool RESID>
__global__ void __launch_bounds__(256) gemm_kernel(
    const float* __restrict__ A, const float* __restrict__ B,
    const float* __restrict__ bias, const float* __restrict__ resid,
    float* __restrict__ C, int M, int N, int K)
{
    __shared__ float As[BK * TPAD];
    __shared__ float Bs[BK * TPAD];

    const int tid = threadIdx.x;
    const int m0 = blockIdx.y * BM;
    const int n0 = blockIdx.x * BN;

    const int lr = tid >> 2;          // 0..63  (row within half-tile)
    const int lk = (tid & 3) * 4;     // k offset {0,4,8,12}
    const int ty = tid >> 4;          // 0..15 (m fragment)
    const int tx = tid & 15;          // 0..15 (n fragment)

    float acc[8][8];
    #pragma unroll
    for (int i = 0; i < 8; i++)
        #pragma unroll
        for (int j = 0; j < 8; j++) acc[i][j] = 0.f;

    for (int k0 = 0; k0 < K; k0 += BK) {
        // global loads (issued early)
        float4 a0 = *(const float4*)(A + (size_t)(m0 + lr)      * K + k0 + lk);
        float4 a1 = *(const float4*)(A + (size_t)(m0 + lr + 64) * K + k0 + lk);
        float4 b0 = *(const float4*)(B + (size_t)(n0 + lr)      * K + k0 + lk);
        float4 b1 = *(const float4*)(B + (size_t)(n0 + lr + 64) * K + k0 + lk);

        __syncthreads();
        As[(lk + 0) * TPAD + lr] = a0.x;
        As[(lk + 1) * TPAD + lr] = a0.y;
        As[(lk + 2) * TPAD + lr] = a0.z;
        As[(lk + 3) * TPAD + lr] = a0.w;
        As[(lk + 0) * TPAD + lr + 64] = a1.x;
        As[(lk + 1) * TPAD + lr + 64] = a1.y;
        As[(lk + 2) * TPAD + lr + 64] = a1.z;
        As[(lk + 3) * TPAD + lr + 64] = a1.w;
        Bs[(lk + 0) * TPAD + lr] = b0.x;
        Bs[(lk + 1) * TPAD + lr] = b0.y;
        Bs[(lk + 2) * TPAD + lr] = b0.z;
        Bs[(lk + 3) * TPAD + lr] = b0.w;
        Bs[(lk + 0) * TPAD + lr + 64] = b1.x;
        Bs[(lk + 1) * TPAD + lr + 64] = b1.y;
        Bs[(lk + 2) * TPAD + lr + 64] = b1.z;
        Bs[(lk + 3) * TPAD + lr + 64] = b1.w;
        __syncthreads();

        #pragma unroll
        for (int kk = 0; kk < BK; kk++) {
            float4 af0 = *(const float4*)&As[kk * TPAD + ty * 4];
            float4 af1 = *(const float4*)&As[kk * TPAD + 64 + ty * 4];
            float4 bf0 = *(const float4*)&Bs[kk * TPAD + tx * 4];
            float4 bf1 = *(const float4*)&Bs[kk * TPAD + 64 + tx * 4];
            float af[8] = {af0.x, af0.y, af0.z, af0.w, af1.x, af1.y, af1.z, af1.w};
            float bf[8] = {bf0.x, bf0.y, bf0.z, bf0.w, bf1.x, bf1.y, bf1.z, bf1.w};
            #pragma unroll
            for (int i = 0; i < 8; i++)
                #pragma unroll
                for (int j = 0; j < 8; j++)
                    acc[i][j] = fmaf(af[i], bf[j], acc[i][j]);
        }
    }

    // epilogue
    #pragma unroll
    for (int ig = 0; ig < 2; ig++) {
        #pragma unroll
        for (int ii = 0; ii < 4; ii++) {
            const int m = m0 + ig * 64 + ty * 4 + ii;
            #pragma unroll
            for (int jg = 0; jg < 2; jg++) {
                const int n = n0 + jg * 64 + tx * 4;
                float4 bs = *(const float4*)(bias + n);
                float4 o;
                o.x = acc[ig * 4 + ii][jg * 4 + 0] + bs.x;
                o.y = acc[ig * 4 + ii][jg * 4 + 1] + bs.y;
                o.z = acc[ig * 4 + ii][jg * 4 + 2] + bs.z;
                o.w = acc[ig * 4 + ii][jg * 4 + 3] + bs.w;
                if (RESID) {
                    float4 r4 = *(const float4*)(resid + (size_t)m * N + n);
                    o.x += r4.x; o.y += r4.y; o.z += r4.z; o.w += r4.w;
                }
                if (GELU) {
                    o.x = gelu_exact(o.x); o.y = gelu_exact(o.y);
                    o.z = gelu_exact(o.z); o.w = gelu_exact(o.w);
                }
                *(float4*)(C + (size_t)m * N + n) = o;
            }
        }
    }
}

// ---------------------------------------------------------------------------
// Banded causal attention, flash-style.
// Block: (q-tile of 64) x (b,h). 256 threads.
// qkv: [4096, 3072]  q at col h*64, k at 1024+h*64, v at 2048+h*64
// ctx: [4096, 1024]
// ---------------------------------------------------------------------------
#define QPAD 65
#define ATTN_SMEM ((3 * 64 * QPAD + 64 * 64 + 3 * 64 + 256) * 4)

__global__ void __launch_bounds__(256) attn_kernel(
    const float* __restrict__ qkv, float* __restrict__ ctx)
{
    extern __shared__ float sm[];
    float* Qs    = sm;                   // 64 x 65
    float* Ks    = Qs + 64 * QPAD;       // 64 x 65
    float* Ps    = Ks + 64 * QPAD;       // 64 x 65
    float* Vs    = Ps + 64 * QPAD;       // 64 x 64
    float* row_m = Vs + 64 * 64;         // 64
    float* row_l = row_m + 64;           // 64
    float* row_a = row_l + 64;           // 64
    float* red   = row_a + 64;           // 64 x 4

    const int t  = threadIdx.x;
    const int bh = blockIdx.y;
    const int b  = bh >> 4, h = bh & 15;
    const int q0 = blockIdx.x * 64;
    const size_t base = (size_t)b * 1024 * 3072 + (size_t)h * 64;

    // load + scale Q
    {
        const int r = t >> 2, c = (t & 3) * 16;
        #pragma unroll
        for (int cc = 0; cc < 16; cc += 4) {
            float4 v = *(const float4*)(qkv + base + (size_t)(q0 + r) * 3072 + c + cc);
            Qs[r * QPAD + c + cc + 0] = v.x * 0.125f;
            Qs[r * QPAD + c + cc + 1] = v.y * 0.125f;
            Qs[r * QPAD + c + cc + 2] = v.z * 0.125f;
            Qs[r * QPAD + c + cc + 3] = v.w * 0.125f;
        }
    }
    if (t < 64) { row_m[t] = -1e30f; row_l[t] = 0.f; }

    float acc[4][4];
    #pragma unroll
    for (int i = 0; i < 4; i++)
        #pragma unroll
        for (int j = 0; j < 4; j++) acc[i][j] = 0.f;

    const int qs = (t & 15) * 4;   // PV: query fragment
    const int ds = (t >> 4) * 4;   // PV: dim fragment
    const int iq = (t >> 4) * 4;   // S: query fragment
    const int jk = (t & 15) * 4;   // S: key fragment
    const int i_row = t & 63, grp = t >> 6;

    const int kt_lo = (q0 >= WIN) ? ((q0 - (WIN - 1)) >> 6) : 0;
    const int kt_hi = q0 >> 6;

    for (int kt = kt_lo; kt <= kt_hi; kt++) {
        const int k0 = kt * 64;
        __syncthreads();
        // load K,V tiles
        {
            const int r = t >> 2, c = (t & 3) * 16;
            #pragma unroll
            for (int cc = 0; cc < 16; cc += 4) {
                float4 kv = *(const float4*)(qkv + base + (size_t)(k0 + r) * 3072 + 1024 + c + cc);
                Ks[r * QPAD + c + cc + 0] = kv.x;
                Ks[r * QPAD + c + cc + 1] = kv.y;
                Ks[r * QPAD + c + cc + 2] = kv.z;
                Ks[r * QPAD + c + cc + 3] = kv.w;
                float4 vv = *(const float4*)(qkv + base + (size_t)(k0 + r) * 3072 + 2048 + c + cc);
                *(float4*)&Vs[r * 64 + c + cc] = vv;
            }
        }
        __syncthreads();

        // S = Q K^T (masked)
        float s[4][4];
        #pragma unroll
        for (int i = 0; i < 4; i++)
            #pragma unroll
            for (int j = 0; j < 4; j++) s[i][j] = 0.f;
        #pragma unroll 8
        for (int d = 0; d < 64; d++) {
            float qf[4], kf[4];
            #pragma unroll
            for (int ii = 0; ii < 4; ii++) qf[ii] = Qs[(iq + ii) * QPAD + d];
            #pragma unroll
            for (int jj = 0; jj < 4; jj++) kf[jj] = Ks[(jk + jj) * QPAD + d];
            #pragma unroll
            for (int ii = 0; ii < 4; ii++)
                #pragma unroll
                for (int jj = 0; jj < 4; jj++)
                    s[ii][jj] = fmaf(qf[ii], kf[jj], s[ii][jj]);
        }
        #pragma unroll
        for (int ii = 0; ii < 4; ii++) {
            const int qi = q0 + iq + ii;
            #pragma unroll
            for (int jj = 0; jj < 4; jj++) {
                const int kj = k0 + jk + jj;
                const bool ok = (kj <= qi) && (qi - kj < WIN);
                Ps[(iq + ii) * QPAD + jk + jj] = ok ? s[ii][jj] : -1e30f;
            }
        }
        __syncthreads();

        // softmax: partial max
        {
            float pm = -1e30f;
            #pragma unroll
            for (int jj = 0; jj < 16; jj++)
                pm = fmaxf(pm, Ps[i_row * QPAD + grp * 16 + jj]);
            red[i_row * 4 + grp] = pm;
        }
        __syncthreads();
        if (t < 64) {
            const float mo = row_m[t];
            float mx = fmaxf(fmaxf(red[t * 4 + 0], red[t * 4 + 1]),
                             fmaxf(red[t * 4 + 2], red[t * 4 + 3]));
            mx = fmaxf(mx, mo);
            row_a[t] = expf(mo - mx);
            row_m[t] = mx;
        }
        __syncthreads();
        // exp + partial sum
        {
            const float m = row_m[i_row];
            float psum = 0.f;
            #pragma unroll
            for (int jj = 0; jj < 16; jj++) {
                const float sv = Ps[i_row * QPAD + grp * 16 + jj];
                const float p = (sv > -1e29f) ? expf(sv - m) : 0.f;
                Ps[i_row * QPAD + grp * 16 + jj] = p;
                psum += p;
            }
            red[i_row * 4 + grp] = psum;
        }
        __syncthreads();
        if (t < 64)
            row_l[t] = row_l[t] * row_a[t] +
                       red[t * 4 + 0] + red[t * 4 + 1] + red[t * 4 + 2] + red[t * 4 + 3];

        // PV accumulate (rescale first)
        float al[4];
        #pragma unroll
        for (int qq = 0; qq < 4; qq++) al[qq] = row_a[qs + qq];
        #pragma unroll
        for (int qq = 0; qq < 4; qq++)
            #pragma unroll
            for (int dd = 0; dd < 4; dd++) acc[qq][dd] *= al[qq];

        #pragma unroll 8
        for (int jj = 0; jj < 64; jj++) {
            float4 v4 = *(const float4*)&Vs[jj * 64 + ds];
            float pf[4];
            #pragma unroll
            for (int qq = 0; qq < 4; qq++) pf[qq] = Ps[(qs + qq) * QPAD + jj];
            #pragma unroll
            for (int qq = 0; qq < 4; qq++) {
                acc[qq][0] = fmaf(pf[qq], v4.x, acc[qq][0]);
                acc[qq][1] = fmaf(pf[qq], v4.y, acc[qq][1]);
                acc[qq][2] = fmaf(pf[qq], v4.z, acc[qq][2]);
                acc[qq][3] = fmaf(pf[qq], v4.w, acc[qq][3]);
            }
        }
    }

    __syncthreads();
    #pragma unroll
    for (int qq = 0; qq < 4; qq++) {
        const float inv = 1.f / row_l[qs + qq];
        float4 o;
        o.x = acc[qq][0] * inv; o.y = acc[qq][1] * inv;
        o.z = acc[qq][2] * inv; o.w = acc[qq][3] * inv;
        *(float4*)(ctx + (size_t)(b * 1024 + q0 + qs + qq) * 1024 + h * 64 + ds) = o;
    }
}

// ---------------------------------------------------------------------------
// LayerNorm: block per row (1024 cols), 256 threads, two-pass in registers
// ---------------------------------------------------------------------------
__global__ void __launch_bounds__(256) ln_kernel(
    const float* __restrict__ in, const float* __restrict__ g,
    const float* __restrict__ be, float* __restrict__ out)
{
    __shared__ float red[8];
    __shared__ float s_mu, s_rs;
    const int t = threadIdx.x;
    const size_t row = blockIdx.x;

    float4 v = ((const float4*)(in + row * 1024))[t];
    float sum = v.x + v.y + v.z + v.w;
    #pragma unroll
    for (int o = 16; o; o >>= 1) sum += __shfl_xor_sync(~0u, sum, o);
    if ((t & 31) == 0) red[t >> 5] = sum;
    __syncthreads();
    if (t == 0) {
        float s = 0.f;
        #pragma unroll
        for (int i = 0; i < 8; i++) s += red[i];
        s_mu = s * (1.f / 1024.f);
    }
    __syncthreads();
    const float mu = s_mu;
    const float dx = v.x - mu, dy = v.y - mu, dz = v.z - mu, dw = v.w - mu;
    float sq = dx * dx + dy * dy + dz * dz + dw * dw;
    #pragma unroll
    for (int o = 16; o; o >>= 1) sq += __shfl_xor_sync(~0u, sq, o);
    __syncthreads();  // protect red[] reuse
    if ((t & 31) == 0) red[t >> 5] = sq;
    __syncthreads();
    if (t == 0) {
        float s = 0.f;
        #pragma unroll
        for (int i = 0; i < 8; i++) s += red[i];
        s_rs = rsqrtf(s * (1.f / 1024.f) + 1e-5f);
    }
    __syncthreads();
    const float rs = s_rs;
    float4 gv = ((const float4*)g)[t];
    float4 bv = ((const float4*)be)[t];
    float4 o;
    o.x = dx * rs * gv.x + bv.x;
    o.y = dy * rs * gv.y + bv.y;
    o.z = dz * rs * gv.z + bv.z;
    o.w = dw * rs * gv.w + bv.w;
    ((float4*)(out + row * 1024))[t] = o;
}

// ---------------------------------------------------------------------------
// launch
// ---------------------------------------------------------------------------
extern "C" void kernel_launch(void* const* d_in, const int* in_sizes, int n_in,
                              void* d_out, int out_size)
{
    const float* x    = (const float*)d_in[0];
    const float* Wqkv = (const float*)d_in[1];
    const float* bqkv = (const float*)d_in[2];
    const float* Wo   = (const float*)d_in[3];
    const float* bo   = (const float*)d_in[4];
    const float* W1   = (const float*)d_in[5];
    const float* b1   = (const float*)d_in[6];
    const float* W2   = (const float*)d_in[7];
    const float* b2   = (const float*)d_in[8];
    const float* g1   = (const float*)d_in[9];
    const float* be1  = (const float*)d_in[10];
    const float* g2   = (const float*)d_in[11];
    const float* be2  = (const float*)d_in[12];
    float* out = (float*)d_out;

    float *qkv, *ctx, *y, *x1, *hb;
    cudaGetSymbolAddress((void**)&qkv, g_qkv);
    cudaGetSymbolAddress((void**)&ctx, g_ctx);
    cudaGetSymbolAddress((void**)&y,   g_y);
    cudaGetSymbolAddress((void**)&x1,  g_x1);
    cudaGetSymbolAddress((void**)&hb,  g_h);

    cudaFuncSetAttribute(attn_kernel,
                         cudaFuncAttributeMaxDynamicSharedMemorySize, ATTN_SMEM);

    dim3 thr(256);
    // 1) QKV projection: [4096,3072]
    gemm_kernel<false, false><<<dim3(3072 / BN, TOKENS / BM), thr>>>(
        x, Wqkv, bqkv, nullptr, qkv, TOKENS, 3 * CDIM, CDIM);
    // 2) banded attention -> ctx [4096,1024]
    attn_kernel<<<dim3(1024 / 64, 4 * NHEAD), thr, ATTN_SMEM>>>(qkv, ctx);
    // 3) Wo + bias + residual(x) -> y
    gemm_kernel<false, true><<<dim3(CDIM / BN, TOKENS / BM), thr>>>(
        ctx, Wo, bo, x, y, TOKENS, CDIM, CDIM);
    // 4) LN1 -> x1
    ln_kernel<<<TOKENS, thr>>>(y, g1, be1, x1);
    // 5) W1 + bias + GELU -> h [4096,4096]
    gemm_kernel<true, false><<<dim3(FFDIM / BN, TOKENS / BM), thr>>>(
        x1, W1, b1, nullptr, hb, TOKENS, FFDIM, CDIM);
    // 6) W2 + bias + residual(x1) -> y
    gemm_kernel<false, true><<<dim3(CDIM / BN, TOKENS / BM), thr>>>(
        hb, W2, b2, x1, y, TOKENS, CDIM, FFDIM);
    // 7) LN2 -> out
    ln_kernel<<<TOKENS, thr>>>(y, g2, be2, out);
}

// round 3
// speedup vs baseline: 2.3076x; 2.3076x over previous
#include <cuda_runtime.h>
#include <math.h>
#include <stdint.h>

// ---------------------------------------------------------------------------
// Problem: B=4, T=1024, C=1024, H=16, Dh=64, D_FF=4096, WINDOW=256. M=4096.
// ---------------------------------------------------------------------------
#define TOKENS 4096
#define CDIM   1024
#define FFDIM  4096
#define WIN    256

__device__ float g_qkv[TOKENS * 3 * CDIM];
__device__ float g_ctx[TOKENS * CDIM];
__device__ float g_y[TOKENS * CDIM];
__device__ float g_x1[TOKENS * CDIM];
__device__ float g_h[TOKENS * FFDIM];

// ---------------------------------------------------------------------------
// helpers
// ---------------------------------------------------------------------------
__device__ __forceinline__ uint32_t smem_u32(const void* p) {
    uint32_t a;
    asm("{ .reg .u64 t; cvta.to.shared.u64 t, %1; cvt.u32.u64 %0, t; }"
        : "=r"(a) : "l"(p));
    return a;
}

#define CP_ASYNC16(sa, ga) \
    asm volatile("cp.async.cg.shared.global [%0], [%1], 16;" :: "r"((uint32_t)(sa)), "l"(ga))
#define CP_COMMIT() asm volatile("cp.async.commit_group;" ::: "memory")
#define CP_WAIT(n)  asm volatile("cp.async.wait_group %0;" :: "n"(n) : "memory")

__device__ __forceinline__ uint32_t cvt_tf32(float f) {
    uint32_t u;
    asm("cvt.rna.tf32.f32 %0, %1;" : "=r"(u) : "f"(f));
    return u;
}

__device__ __forceinline__ void mma_tf32(float* d, const uint32_t* a,
                                         uint32_t b0, uint32_t b1) {
    asm volatile(
        "mma.sync.aligned.m16n8k8.row.col.f32.tf32.tf32.f32 "
        "{%0,%1,%2,%3}, {%4,%5,%6,%7}, {%8,%9}, {%0,%1,%2,%3};"
        : "+f"(d[0]), "+f"(d[1]), "+f"(d[2]), "+f"(d[3])
        : "r"(a[0]), "r"(a[1]), "r"(a[2]), "r"(a[3]), "r"(b0), "r"(b1));
}

__device__ __forceinline__ float gelu_exact(float v) {
    return 0.5f * v * (1.0f + erff(v * 0.70710678118654752f));
}

// ---------------------------------------------------------------------------
// tf32 mma.sync GEMM: C[m,n] = sum_k A[m,k]*B[n,k] + bias[n] (+resid)(+gelu)
// CTA 128x128xBK32, 8 warps (4m x 2n), warp tile 32x64, m16n8k8 tf32 MMA.
// 2-stage cp.async double buffer; smem rows padded to 40 floats so the
// float2 fragment loads (k-pairs) are bank-conflict-free.
// k-remap: mma k-slot tig <-> physical 2*tig, slot tig+4 <-> 2*tig+1,
// applied to BOTH A and B (a pure permutation of the reduction order).
// ---------------------------------------------------------------------------
#define GBM 128
#define GBN 128
#define GBK 32
#define GSTRIDE 40
#define GSTG_FLOATS ((GBM + GBN) * GSTRIDE)     // 10240 floats / stage
#define GEMM_SMEM (2 * GSTG_FLOATS * 4)         // 81920 bytes

template <bool GELU, bool RESID>
__global__ void __launch_bounds__(256) tgemm(
    const float* __restrict__ A, const float* __restrict__ B,
    const float* __restrict__ bias, const float* __restrict__ resid,
    float* __restrict__ C, int M, int N, int K)
{
    extern __shared__ float sm[];
    const int tid  = threadIdx.x;
    const int wid  = tid >> 5, lane = tid & 31;
    const int wm   = wid >> 1, wn = wid & 1;
    const int g    = lane >> 2, tg = lane & 3;
    const int m0   = blockIdx.y * GBM;
    const int n0   = blockIdx.x * GBN;
    const int niter = K / GBK;

    float acc[2][8][4];
    #pragma unroll
    for (int i = 0; i < 2; i++)
        #pragma unroll
        for (int j = 0; j < 8; j++)
            #pragma unroll
            for (int k = 0; k < 4; k++) acc[i][j][k] = 0.f;

    // loader mapping: 1024 float4 per tile per stage, 4 per thread
    const int lrow0 = tid >> 3;          // +64 per i (idx>>3 with idx=tid+i*256)
    const int lc4   = (tid & 7) * 4;

#define LOADC(j) do {                                                          \
    const int _st = (j) & 1;                                                   \
    float* _dA = sm + _st * GSTG_FLOATS;                                       \
    float* _dB = _dA + GBM * GSTRIDE;                                          \
    const int _k0 = (j) * GBK;                                                 \
    _Pragma("unroll")                                                          \
    for (int i = 0; i < 4; i++) {                                              \
        const int row = lrow0 + i * 32;                                        \
        CP_ASYNC16(smem_u32(_dA + row * GSTRIDE + lc4),                        \
                   A + (size_t)(m0 + row) * K + _k0 + lc4);                    \
        CP_ASYNC16(smem_u32(_dB + row * GSTRIDE + lc4),                        \
                   B + (size_t)(n0 + row) * K + _k0 + lc4);                    \
    }                                                                          \
} while (0)

    LOADC(0); CP_COMMIT();

    for (int j = 0; j < niter; j++) {
        if (j + 1 < niter) { LOADC(j + 1); CP_COMMIT(); CP_WAIT(1); }
        else               { CP_WAIT(0); }
        __syncthreads();

        const float* sA = sm + (j & 1) * GSTG_FLOATS + (wm * 32) * GSTRIDE;
        const float* sB = sm + (j & 1) * GSTG_FLOATS + GBM * GSTRIDE
                          + (wn * 64) * GSTRIDE;

        #pragma unroll
        for (int s = 0; s < 4; s++) {
            const int kc = s * 8 + 2 * tg;
            uint32_t a[2][4];
            #pragma unroll
            for (int mi = 0; mi < 2; mi++) {
                float2 lo = *(const float2*)&sA[(mi * 16 + g) * GSTRIDE + kc];
                float2 hi = *(const float2*)&sA[(mi * 16 + 8 + g) * GSTRIDE + kc];
                a[mi][0] = cvt_tf32(lo.x);
                a[mi][1] = cvt_tf32(hi.x);
                a[mi][2] = cvt_tf32(lo.y);
                a[mi][3] = cvt_tf32(hi.y);
            }
            #pragma unroll
            for (int ni = 0; ni < 8; ni++) {
                float2 bv = *(const float2*)&sB[(ni * 8 + g) * GSTRIDE + kc];
                const uint32_t b0 = cvt_tf32(bv.x);
                const uint32_t b1 = cvt_tf32(bv.y);
                mma_tf32(acc[0][ni], a[0], b0, b1);
                mma_tf32(acc[1][ni], a[1], b0, b1);
            }
        }
        __syncthreads();
    }

    // epilogue: c0,c1 -> (row g, cols 2tg,2tg+1); c2,c3 -> (row g+8, same cols)
    #pragma unroll
    for (int mi = 0; mi < 2; mi++) {
        #pragma unroll
        for (int rr = 0; rr < 2; rr++) {
            const int m = m0 + wm * 32 + mi * 16 + rr * 8 + g;
            float* crow = C + (size_t)m * N;
            const float* rrow = RESID ? (resid + (size_t)m * N) : nullptr;
            #pragma unroll
            for (int ni = 0; ni < 8; ni++) {
                const int n = n0 + wn * 64 + ni * 8 + 2 * tg;
                float ox = acc[mi][ni][rr * 2 + 0] + bias[n];
                float oy = acc[mi][ni][rr * 2 + 1] + bias[n + 1];
                if (RESID) { ox += rrow[n]; oy += rrow[n + 1]; }
                if (GELU)  { ox = gelu_exact(ox); oy = gelu_exact(oy); }
                float2 o = make_float2(ox, oy);
                *(float2*)(crow + n) = o;
            }
        }
    }
}

// ---------------------------------------------------------------------------
// Banded causal attention, flash-style (fp32 SIMT). Unchanged from R1.
// ---------------------------------------------------------------------------
#define QPAD 65
#define ATTN_SMEM ((3 * 64 * QPAD + 64 * 64 + 3 * 64 + 256) * 4)

__global__ void __launch_bounds__(256) attn_kernel(
    const float* __restrict__ qkv, float* __restrict__ ctx)
{
    extern __shared__ float smf[];
    float* Qs    = smf;
    float* Ks    = Qs + 64 * QPAD;
    float* Ps    = Ks + 64 * QPAD;
    float* Vs    = Ps + 64 * QPAD;
    float* row_m = Vs + 64 * 64;
    float* row_l = row_m + 64;
    float* row_a = row_l + 64;
    float* red   = row_a + 64;

    const int t  = threadIdx.x;
    const int bh = blockIdx.y;
    const int b  = bh >> 4, h = bh & 15;
    const int q0 = blockIdx.x * 64;
    const size_t base = (size_t)b * 1024 * 3072 + (size_t)h * 64;

    {
        const int r = t >> 2, c = (t & 3) * 16;
        #pragma unroll
        for (int cc = 0; cc < 16; cc += 4) {
            float4 v = *(const float4*)(qkv + base + (size_t)(q0 + r) * 3072 + c + cc);
            Qs[r * QPAD + c + cc + 0] = v.x * 0.125f;
            Qs[r * QPAD + c + cc + 1] = v.y * 0.125f;
            Qs[r * QPAD + c + cc + 2] = v.z * 0.125f;
            Qs[r * QPAD + c + cc + 3] = v.w * 0.125f;
        }
    }
    if (t < 64) { row_m[t] = -1e30f; row_l[t] = 0.f; }

    float acc[4][4];
    #pragma unroll
    for (int i = 0; i < 4; i++)
        #pragma unroll
        for (int j = 0; j < 4; j++) acc[i][j] = 0.f;

    const int qs = (t & 15) * 4;
    const int ds = (t >> 4) * 4;
    const int iq = (t >> 4) * 4;
    const int jk = (t & 15) * 4;
    const int i_row = t & 63, grp = t >> 6;

    const int kt_lo = (q0 >= WIN) ? ((q0 - (WIN - 1)) >> 6) : 0;
    const int kt_hi = q0 >> 6;

    for (int kt = kt_lo; kt <= kt_hi; kt++) {
        const int k0 = kt * 64;
        __syncthreads();
        {
            const int r = t >> 2, c = (t & 3) * 16;
            #pragma unroll
            for (int cc = 0; cc < 16; cc += 4) {
                float4 kv = *(const float4*)(qkv + base + (size_t)(k0 + r) * 3072 + 1024 + c + cc);
                Ks[r * QPAD + c + cc + 0] = kv.x;
                Ks[r * QPAD + c + cc + 1] = kv.y;
                Ks[r * QPAD + c + cc + 2] = kv.z;
                Ks[r * QPAD + c + cc + 3] = kv.w;
                float4 vv = *(const float4*)(qkv + base + (size_t)(k0 + r) * 3072 + 2048 + c + cc);
                *(float4*)&Vs[r * 64 + c + cc] = vv;
            }
        }
        __syncthreads();

        float s[4][4];
        #pragma unroll
        for (int i = 0; i < 4; i++)
            #pragma unroll
            for (int j = 0; j < 4; j++) s[i][j] = 0.f;
        #pragma unroll 8
        for (int d = 0; d < 64; d++) {
            float qf[4], kf[4];
            #pragma unroll
            for (int ii = 0; ii < 4; ii++) qf[ii] = Qs[(iq + ii) * QPAD + d];
            #pragma unroll
            for (int jj = 0; jj < 4; jj++) kf[jj] = Ks[(jk + jj) * QPAD + d];
            #pragma unroll
            for (int ii = 0; ii < 4; ii++)
                #pragma unroll
                for (int jj = 0; jj < 4; jj++)
                    s[ii][jj] = fmaf(qf[ii], kf[jj], s[ii][jj]);
        }
        #pragma unroll
        for (int ii = 0; ii < 4; ii++) {
            const int qi = q0 + iq + ii;
            #pragma unroll
            for (int jj = 0; jj < 4; jj++) {
                const int kj = k0 + jk + jj;
                const bool ok = (kj <= qi) && (qi - kj < WIN);
                Ps[(iq + ii) * QPAD + jk + jj] = ok ? s[ii][jj] : -1e30f;
            }
        }
        __syncthreads();

        {
            float pm = -1e30f;
            #pragma unroll
            for (int jj = 0; jj < 16; jj++)
                pm = fmaxf(pm, Ps[i_row * QPAD + grp * 16 + jj]);
            red[i_row * 4 + grp] = pm;
        }
        __syncthreads();
        if (t < 64) {
            const float mo = row_m[t];
            float mx = fmaxf(fmaxf(red[t * 4 + 0], red[t * 4 + 1]),
                             fmaxf(red[t * 4 + 2], red[t * 4 + 3]));
            mx = fmaxf(mx, mo);
            row_a[t] = expf(mo - mx);
            row_m[t] = mx;
        }
        __syncthreads();
        {
            const float m = row_m[i_row];
            float psum = 0.f;
            #pragma unroll
            for (int jj = 0; jj < 16; jj++) {
                const float sv = Ps[i_row * QPAD + grp * 16 + jj];
                const float p = (sv > -1e29f) ? expf(sv - m) : 0.f;
                Ps[i_row * QPAD + grp * 16 + jj] = p;
                psum += p;
            }
            red[i_row * 4 + grp] = psum;
        }
        __syncthreads();
        if (t < 64)
            row_l[t] = row_l[t] * row_a[t] +
                       red[t * 4 + 0] + red[t * 4 + 1] + red[t * 4 + 2] + red[t * 4 + 3];

        float al[4];
        #pragma unroll
        for (int qq = 0; qq < 4; qq++) al[qq] = row_a[qs + qq];
        #pragma unroll
        for (int qq = 0; qq < 4; qq++)
            #pragma unroll
            for (int dd = 0; dd < 4; dd++) acc[qq][dd] *= al[qq];

        #pragma unroll 8
        for (int jj = 0; jj < 64; jj++) {
            float4 v4 = *(const float4*)&Vs[jj * 64 + ds];
            float pf[4];
            #pragma unroll
            for (int qq = 0; qq < 4; qq++) pf[qq] = Ps[(qs + qq) * QPAD + jj];
            #pragma unroll
            for (int qq = 0; qq < 4; qq++) {
                acc[qq][0] = fmaf(pf[qq], v4.x, acc[qq][0]);
                acc[qq][1] = fmaf(pf[qq], v4.y, acc[qq][1]);
                acc[qq][2] = fmaf(pf[qq], v4.z, acc[qq][2]);
                acc[qq][3] = fmaf(pf[qq], v4.w, acc[qq][3]);
            }
        }
    }

    __syncthreads();
    #pragma unroll
    for (int qq = 0; qq < 4; qq++) {
        const float inv = 1.f / row_l[qs + qq];
        float4 o;
        o.x = acc[qq][0] * inv; o.y = acc[qq][1] * inv;
        o.z = acc[qq][2] * inv; o.w = acc[qq][3] * inv;
        *(float4*)(ctx + (size_t)(b * 1024 + q0 + qs + qq) * 1024 + h * 64 + ds) = o;
    }
}

// ---------------------------------------------------------------------------
// LayerNorm (unchanged)
// ---------------------------------------------------------------------------
__global__ void __launch_bounds__(256) ln_kernel(
    const float* __restrict__ in, const float* __restrict__ g,
    const float* __restrict__ be, float* __restrict__ out)
{
    __shared__ float red[8];
    __shared__ float s_mu, s_rs;
    const int t = threadIdx.x;
    const size_t row = blockIdx.x;

    float4 v = ((const float4*)(in + row * 1024))[t];
    float sum = v.x + v.y + v.z + v.w;
    #pragma unroll
    for (int o = 16; o; o >>= 1) sum += __shfl_xor_sync(~0u, sum, o);
    if ((t & 31) == 0) red[t >> 5] = sum;
    __syncthreads();
    if (t == 0) {
        float s = 0.f;
        #pragma unroll
        for (int i = 0; i < 8; i++) s += red[i];
        s_mu = s * (1.f / 1024.f);
    }
    __syncthreads();
    const float mu = s_mu;
    const float dx = v.x - mu, dy = v.y - mu, dz = v.z - mu, dw = v.w - mu;
    float sq = dx * dx + dy * dy + dz * dz + dw * dw;
    #pragma unroll
    for (int o = 16; o; o >>= 1) sq += __shfl_xor_sync(~0u, sq, o);
    __syncthreads();
    if ((t & 31) == 0) red[t >> 5] = sq;
    __syncthreads();
    if (t == 0) {
        float s = 0.f;
        #pragma unroll
        for (int i = 0; i < 8; i++) s += red[i];
        s_rs = rsqrtf(s * (1.f / 1024.f) + 1e-5f);
    }
    __syncthreads();
    const float rs = s_rs;
    float4 gv = ((const float4*)g)[t];
    float4 bv = ((const float4*)be)[t];
    float4 o;
    o.x = dx * rs * gv.x + bv.x;
    o.y = dy * rs * gv.y + bv.y;
    o.z = dz * rs * gv.z + bv.z;
    o.w = dw * rs * gv.w + bv.w;
    ((float4*)(out + row * 1024))[t] = o;
}

// ---------------------------------------------------------------------------
// launch
// ---------------------------------------------------------------------------
extern "C" void kernel_launch(void* const* d_in, const int* in_sizes, int n_in,
                              void* d_out, int out_size)
{
    const float* x    = (const float*)d_in[0];
    const float* Wqkv = (const float*)d_in[1];
    const float* bqkv = (const float*)d_in[2];
    const float* Wo   = (const float*)d_in[3];
    const float* bo   = (const float*)d_in[4];
    const float* W1   = (const float*)d_in[5];
    const float* b1   = (const float*)d_in[6];
    const float* W2   = (const float*)d_in[7];
    const float* b2   = (const float*)d_in[8];
    const float* g1   = (const float*)d_in[9];
    const float* be1  = (const float*)d_in[10];
    const float* g2   = (const float*)d_in[11];
    const float* be2  = (const float*)d_in[12];
    float* out = (float*)d_out;

    float *qkv, *ctx, *y, *x1, *hb;
    cudaGetSymbolAddress((void**)&qkv, g_qkv);
    cudaGetSymbolAddress((void**)&ctx, g_ctx);
    cudaGetSymbolAddress((void**)&y,   g_y);
    cudaGetSymbolAddress((void**)&x1,  g_x1);
    cudaGetSymbolAddress((void**)&hb,  g_h);

    cudaFuncSetAttribute(attn_kernel,
                         cudaFuncAttributeMaxDynamicSharedMemorySize, ATTN_SMEM);
    cudaFuncSetAttribute(tgemm<false, false>,
                         cudaFuncAttributeMaxDynamicSharedMemorySize, GEMM_SMEM);
    cudaFuncSetAttribute(tgemm<false, true>,
                         cudaFuncAttributeMaxDynamicSharedMemorySize, GEMM_SMEM);
    cudaFuncSetAttribute(tgemm<true, false>,
                         cudaFuncAttributeMaxDynamicSharedMemorySize, GEMM_SMEM);

    dim3 thr(256);
    // 1) QKV projection
    tgemm<false, false><<<dim3(3072 / GBN, TOKENS / GBM), thr, GEMM_SMEM>>>(
        x, Wqkv, bqkv, nullptr, qkv, TOKENS, 3 * CDIM, CDIM);
    // 2) banded attention
    attn_kernel<<<dim3(1024 / 64, 4 * 16), thr, ATTN_SMEM>>>(qkv, ctx);
    // 3) Wo + bias + residual(x)
    tgemm<false, true><<<dim3(CDIM / GBN, TOKENS / GBM), thr, GEMM_SMEM>>>(
        ctx, Wo, bo, x, y, TOKENS, CDIM, CDIM);
    // 4) LN1
    ln_kernel<<<TOKENS, thr>>>(y, g1, be1, x1);
    // 5) W1 + bias + GELU
    tgemm<true, false><<<dim3(FFDIM / GBN, TOKENS / GBM), thr, GEMM_SMEM>>>(
        x1, W1, b1, nullptr, hb, TOKENS, FFDIM, CDIM);
    // 6) W2 + bias + residual(x1)
    tgemm<false, true><<<dim3(CDIM / GBN, TOKENS / GBM), thr, GEMM_SMEM>>>(
        hb, W2, b2, x1, y, TOKENS, CDIM, FFDIM);
    // 7) LN2
    ln_kernel<<<TOKENS, thr>>>(y, g2, be2, out);
}

// round 4
// speedup vs baseline: 2.5799x; 1.1180x over previous
#include <cuda_runtime.h>
#include <math.h>
#include <stdint.h>

// ---------------------------------------------------------------------------
// Problem: B=4, T=1024, C=1024, H=16, Dh=64, D_FF=4096, WINDOW=256. M=4096.
// ---------------------------------------------------------------------------
#define TOKENS 4096
#define CDIM   1024
#define FFDIM  4096
#define WIN    256

__device__ float g_qkv[TOKENS * 3 * CDIM];
__device__ float g_ctx[TOKENS * CDIM];     // tf32-rounded at write
__device__ float g_y[TOKENS * CDIM];
__device__ float g_x1[TOKENS * CDIM];      // exact (residual use)
__device__ float g_x1r[TOKENS * CDIM];     // tf32-rounded (GEMM input)
__device__ float g_h[TOKENS * FFDIM];      // tf32-rounded at write (GELU out)
__device__ float g_xr[TOKENS * CDIM];      // tf32-rounded copy of x
__device__ float g_wqkvr[3 * CDIM * CDIM];
__device__ float g_wor[CDIM * CDIM];
__device__ float g_w1r[FFDIM * CDIM];
__device__ float g_w2r[CDIM * FFDIM];

// ---------------------------------------------------------------------------
// helpers
// ---------------------------------------------------------------------------
__device__ __forceinline__ uint32_t smem_u32(const void* p) {
    uint32_t a;
    asm("{ .reg .u64 t; cvta.to.shared.u64 t, %1; cvt.u32.u64 %0, t; }"
        : "=r"(a) : "l"(p));
    return a;
}

#define CP_ASYNC16(sa, ga) \
    asm volatile("cp.async.cg.shared.global [%0], [%1], 16;" :: "r"((uint32_t)(sa)), "l"(ga))
#define CP_COMMIT() asm volatile("cp.async.commit_group;" ::: "memory")
#define CP_WAIT(n)  asm volatile("cp.async.wait_group %0;" :: "n"(n) : "memory")

__device__ __forceinline__ float round_tf32(float f) {
    uint32_t u;
    asm("cvt.rna.tf32.f32 %0, %1;" : "=r"(u) : "f"(f));
    return __uint_as_float(u);
}

__device__ __forceinline__ void mma_tf32(float* d, const uint32_t* a,
                                         uint32_t b0, uint32_t b1) {
    asm volatile(
        "mma.sync.aligned.m16n8k8.row.col.f32.tf32.tf32.f32 "
        "{%0,%1,%2,%3}, {%4,%5,%6,%7}, {%8,%9}, {%0,%1,%2,%3};"
        : "+f"(d[0]), "+f"(d[1]), "+f"(d[2]), "+f"(d[3])
        : "r"(a[0]), "r"(a[1]), "r"(a[2]), "r"(a[3]), "r"(b0), "r"(b1));
}

__device__ __forceinline__ float gelu_exact(float v) {
    return 0.5f * v * (1.0f + erff(v * 0.70710678118654752f));
}

// ---------------------------------------------------------------------------
// elementwise tf32 rounding pass (for weights / x)
// ---------------------------------------------------------------------------
__global__ void __launch_bounds__(256) round_kernel(
    const float* __restrict__ in, float* __restrict__ out, int n4)
{
    const int i = blockIdx.x * 256 + threadIdx.x;
    if (i < n4) {
        float4 v = ((const float4*)in)[i];
        v.x = round_tf32(v.x); v.y = round_tf32(v.y);
        v.z = round_tf32(v.z); v.w = round_tf32(v.w);
        ((float4*)out)[i] = v;
    }
}

// ---------------------------------------------------------------------------
// tf32 mma.sync GEMM (inputs pre-rounded to tf32 bit patterns; no in-loop cvt)
// CTA 128x128xBK32, 8 warps (4m x 2n), warp tile 32x64, m16n8k8.
// 2-stage cp.async double buffer; smem rows padded to 40 floats.
// k-slot permutation applied equally to A and B (reduction-order permutation).
// ---------------------------------------------------------------------------
#define GBM 128
#define GBN 128
#define GBK 32
#define GSTRIDE 40
#define GSTG_FLOATS ((GBM + GBN) * GSTRIDE)     // 10240 floats / stage
#define GEMM_SMEM (2 * GSTG_FLOATS * 4)         // 81920 bytes

template <bool GELU, bool RESID, bool ROUND>
__global__ void __launch_bounds__(256) tgemm(
    const float* __restrict__ A, const float* __restrict__ B,
    const float* __restrict__ bias, const float* __restrict__ resid,
    float* __restrict__ C, int M, int N, int K)
{
    extern __shared__ float sm[];
    const int tid  = threadIdx.x;
    const int wid  = tid >> 5, lane = tid & 31;
    const int wm   = wid >> 1, wn = wid & 1;
    const int g    = lane >> 2, tg = lane & 3;
    const int m0   = blockIdx.y * GBM;
    const int n0   = blockIdx.x * GBN;
    const int niter = K / GBK;

    float acc[2][8][4];
    #pragma unroll
    for (int i = 0; i < 2; i++)
        #pragma unroll
        for (int j = 0; j < 8; j++)
            #pragma unroll
            for (int k = 0; k < 4; k++) acc[i][j][k] = 0.f;

    const int lrow0 = tid >> 3;
    const int lc4   = (tid & 7) * 4;

#define LOADC(j) do {                                                          \
    const int _st = (j) & 1;                                                   \
    float* _dA = sm + _st * GSTG_FLOATS;                                       \
    float* _dB = _dA + GBM * GSTRIDE;                                          \
    const int _k0 = (j) * GBK;                                                 \
    _Pragma("unroll")                                                          \
    for (int i = 0; i < 4; i++) {                                              \
        const int row = lrow0 + i * 32;                                        \
        CP_ASYNC16(smem_u32(_dA + row * GSTRIDE + lc4),                        \
                   A + (size_t)(m0 + row) * K + _k0 + lc4);                    \
        CP_ASYNC16(smem_u32(_dB + row * GSTRIDE + lc4),                        \
                   B + (size_t)(n0 + row) * K + _k0 + lc4);                    \
    }                                                                          \
} while (0)

    LOADC(0); CP_COMMIT();

    for (int j = 0; j < niter; j++) {
        if (j + 1 < niter) { LOADC(j + 1); CP_COMMIT(); CP_WAIT(1); }
        else               { CP_WAIT(0); }
        __syncthreads();

        const float* sA = sm + (j & 1) * GSTG_FLOATS + (wm * 32) * GSTRIDE;
        const float* sB = sm + (j & 1) * GSTG_FLOATS + GBM * GSTRIDE
                          + (wn * 64) * GSTRIDE;

        #pragma unroll
        for (int s = 0; s < 4; s++) {
            const int kc = s * 8 + 2 * tg;
            uint32_t a[2][4];
            #pragma unroll
            for (int mi = 0; mi < 2; mi++) {
                float2 lo = *(const float2*)&sA[(mi * 16 + g) * GSTRIDE + kc];
                float2 hi = *(const float2*)&sA[(mi * 16 + 8 + g) * GSTRIDE + kc];
                a[mi][0] = __float_as_uint(lo.x);
                a[mi][1] = __float_as_uint(hi.x);
                a[mi][2] = __float_as_uint(lo.y);
                a[mi][3] = __float_as_uint(hi.y);
            }
            #pragma unroll
            for (int ni = 0; ni < 8; ni++) {
                float2 bv = *(const float2*)&sB[(ni * 8 + g) * GSTRIDE + kc];
                const uint32_t b0 = __float_as_uint(bv.x);
                const uint32_t b1 = __float_as_uint(bv.y);
                mma_tf32(acc[0][ni], a[0], b0, b1);
                mma_tf32(acc[1][ni], a[1], b0, b1);
            }
        }
        __syncthreads();
    }

    #pragma unroll
    for (int mi = 0; mi < 2; mi++) {
        #pragma unroll
        for (int rr = 0; rr < 2; rr++) {
            const int m = m0 + wm * 32 + mi * 16 + rr * 8 + g;
            float* crow = C + (size_t)m * N;
            const float* rrow = RESID ? (resid + (size_t)m * N) : nullptr;
            #pragma unroll
            for (int ni = 0; ni < 8; ni++) {
                const int n = n0 + wn * 64 + ni * 8 + 2 * tg;
                float ox = acc[mi][ni][rr * 2 + 0] + bias[n];
                float oy = acc[mi][ni][rr * 2 + 1] + bias[n + 1];
                if (RESID) { ox += rrow[n]; oy += rrow[n + 1]; }
                if (GELU)  { ox = gelu_exact(ox); oy = gelu_exact(oy); }
                if (ROUND) { ox = round_tf32(ox); oy = round_tf32(oy); }
                float2 o = make_float2(ox, oy);
                *(float2*)(crow + n) = o;
            }
        }
    }
}

// ---------------------------------------------------------------------------
// Banded causal attention, flash-style (fp32 SIMT). Output tf32-rounded.
// ---------------------------------------------------------------------------
#define QPAD 65
#define ATTN_SMEM ((3 * 64 * QPAD + 64 * 64 + 3 * 64 + 256) * 4)

__global__ void __launch_bounds__(256) attn_kernel(
    const float* __restrict__ qkv, float* __restrict__ ctx)
{
    extern __shared__ float smf[];
    float* Qs    = smf;
    float* Ks    = Qs + 64 * QPAD;
    float* Ps    = Ks + 64 * QPAD;
    float* Vs    = Ps + 64 * QPAD;
    float* row_m = Vs + 64 * 64;
    float* row_l = row_m + 64;
    float* row_a = row_l + 64;
    float* red   = row_a + 64;

    const int t  = threadIdx.x;
    const int bh = blockIdx.y;
    const int b  = bh >> 4, h = bh & 15;
    const int q0 = blockIdx.x * 64;
    const size_t base = (size_t)b * 1024 * 3072 + (size_t)h * 64;

    {
        const int r = t >> 2, c = (t & 3) * 16;
        #pragma unroll
        for (int cc = 0; cc < 16; cc += 4) {
            float4 v = *(const float4*)(qkv + base + (size_t)(q0 + r) * 3072 + c + cc);
            Qs[r * QPAD + c + cc + 0] = v.x * 0.125f;
            Qs[r * QPAD + c + cc + 1] = v.y * 0.125f;
            Qs[r * QPAD + c + cc + 2] = v.z * 0.125f;
            Qs[r * QPAD + c + cc + 3] = v.w * 0.125f;
        }
    }
    if (t < 64) { row_m[t] = -1e30f; row_l[t] = 0.f; }

    float acc[4][4];
    #pragma unroll
    for (int i = 0; i < 4; i++)
        #pragma unroll
        for (int j = 0; j < 4; j++) acc[i][j] = 0.f;

    const int qs = (t & 15) * 4;
    const int ds = (t >> 4) * 4;
    const int iq = (t >> 4) * 4;
    const int jk = (t & 15) * 4;
    const int i_row = t & 63, grp = t >> 6;

    const int kt_lo = (q0 >= WIN) ? ((q0 - (WIN - 1)) >> 6) : 0;
    const int kt_hi = q0 >> 6;

    for (int kt = kt_lo; kt <= kt_hi; kt++) {
        const int k0 = kt * 64;
        __syncthreads();
        {
            const int r = t >> 2, c = (t & 3) * 16;
            #pragma unroll
            for (int cc = 0; cc < 16; cc += 4) {
                float4 kv = *(const float4*)(qkv + base + (size_t)(k0 + r) * 3072 + 1024 + c + cc);
                Ks[r * QPAD + c + cc + 0] = kv.x;
                Ks[r * QPAD + c + cc + 1] = kv.y;
                Ks[r * QPAD + c + cc + 2] = kv.z;
                Ks[r * QPAD + c + cc + 3] = kv.w;
                float4 vv = *(const float4*)(qkv + base + (size_t)(k0 + r) * 3072 + 2048 + c + cc);
                *(float4*)&Vs[r * 64 + c + cc] = vv;
            }
        }
        __syncthreads();

        float s[4][4];
        #pragma unroll
        for (int i = 0; i < 4; i++)
            #pragma unroll
            for (int j = 0; j < 4; j++) s[i][j] = 0.f;
        #pragma unroll 8
        for (int d = 0; d < 64; d++) {
            float qf[4], kf[4];
            #pragma unroll
            for (int ii = 0; ii < 4; ii++) qf[ii] = Qs[(iq + ii) * QPAD + d];
            #pragma unroll
            for (int jj = 0; jj < 4; jj++) kf[jj] = Ks[(jk + jj) * QPAD + d];
            #pragma unroll
            for (int ii = 0; ii < 4; ii++)
                #pragma unroll
                for (int jj = 0; jj < 4; jj++)
                    s[ii][jj] = fmaf(qf[ii], kf[jj], s[ii][jj]);
        }
        #pragma unroll
        for (int ii = 0; ii < 4; ii++) {
            const int qi = q0 + iq + ii;
            #pragma unroll
            for (int jj = 0; jj < 4; jj++) {
                const int kj = k0 + jk + jj;
                const bool ok = (kj <= qi) && (qi - kj < WIN);
                Ps[(iq + ii) * QPAD + jk + jj] = ok ? s[ii][jj] : -1e30f;
            }
        }
        __syncthreads();

        {
            float pm = -1e30f;
            #pragma unroll
            for (int jj = 0; jj < 16; jj++)
                pm = fmaxf(pm, Ps[i_row * QPAD + grp * 16 + jj]);
            red[i_row * 4 + grp] = pm;
        }
        __syncthreads();
        if (t < 64) {
            const float mo = row_m[t];
            float mx = fmaxf(fmaxf(red[t * 4 + 0], red[t * 4 + 1]),
                             fmaxf(red[t * 4 + 2], red[t * 4 + 3]));
            mx = fmaxf(mx, mo);
            row_a[t] = expf(mo - mx);
            row_m[t] = mx;
        }
        __syncthreads();
        {
            const float m = row_m[i_row];
            float psum = 0.f;
            #pragma unroll
            for (int jj = 0; jj < 16; jj++) {
                const float sv = Ps[i_row * QPAD + grp * 16 + jj];
                const float p = (sv > -1e29f) ? expf(sv - m) : 0.f;
                Ps[i_row * QPAD + grp * 16 + jj] = p;
                psum += p;
            }
            red[i_row * 4 + grp] = psum;
        }
        __syncthreads();
        if (t < 64)
            row_l[t] = row_l[t] * row_a[t] +
                       red[t * 4 + 0] + red[t * 4 + 1] + red[t * 4 + 2] + red[t * 4 + 3];

        float al[4];
        #pragma unroll
        for (int qq = 0; qq < 4; qq++) al[qq] = row_a[qs + qq];
        #pragma unroll
        for (int qq = 0; qq < 4; qq++)
            #pragma unroll
            for (int dd = 0; dd < 4; dd++) acc[qq][dd] *= al[qq];

        #pragma unroll 8
        for (int jj = 0; jj < 64; jj++) {
            float4 v4 = *(const float4*)&Vs[jj * 64 + ds];
            float pf[4];
            #pragma unroll
            for (int qq = 0; qq < 4; qq++) pf[qq] = Ps[(qs + qq) * QPAD + jj];
            #pragma unroll
            for (int qq = 0; qq < 4; qq++) {
                acc[qq][0] = fmaf(pf[qq], v4.x, acc[qq][0]);
                acc[qq][1] = fmaf(pf[qq], v4.y, acc[qq][1]);
                acc[qq][2] = fmaf(pf[qq], v4.z, acc[qq][2]);
                acc[qq][3] = fmaf(pf[qq], v4.w, acc[qq][3]);
            }
        }
    }

    __syncthreads();
    #pragma unroll
    for (int qq = 0; qq < 4; qq++) {
        const float inv = 1.f / row_l[qs + qq];
        float4 o;
        o.x = round_tf32(acc[qq][0] * inv);
        o.y = round_tf32(acc[qq][1] * inv);
        o.z = round_tf32(acc[qq][2] * inv);
        o.w = round_tf32(acc[qq][3] * inv);
        *(float4*)(ctx + (size_t)(b * 1024 + q0 + qs + qq) * 1024 + h * 64 + ds) = o;
    }
}

// ---------------------------------------------------------------------------
// LayerNorm: optional second tf32-rounded output
// ---------------------------------------------------------------------------
__global__ void __launch_bounds__(256) ln_kernel(
    const float* __restrict__ in, const float* __restrict__ g,
    const float* __restrict__ be, float* __restrict__ out,
    float* __restrict__ out_r)
{
    __shared__ float red[8];
    __shared__ float s_mu, s_rs;
    const int t = threadIdx.x;
    const size_t row = blockIdx.x;

    float4 v = ((const float4*)(in + row * 1024))[t];
    float sum = v.x + v.y + v.z + v.w;
    #pragma unroll
    for (int o = 16; o; o >>= 1) sum += __shfl_xor_sync(~0u, sum, o);
    if ((t & 31) == 0) red[t >> 5] = sum;
    __syncthreads();
    if (t == 0) {
        float s = 0.f;
        #pragma unroll
        for (int i = 0; i < 8; i++) s += red[i];
        s_mu = s * (1.f / 1024.f);
    }
    __syncthreads();
    const float mu = s_mu;
    const float dx = v.x - mu, dy = v.y - mu, dz = v.z - mu, dw = v.w - mu;
    float sq = dx * dx + dy * dy + dz * dz + dw * dw;
    #pragma unroll
    for (int o = 16; o; o >>= 1) sq += __shfl_xor_sync(~0u, sq, o);
    __syncthreads();
    if ((t & 31) == 0) red[t >> 5] = sq;
    __syncthreads();
    if (t == 0) {
        float s = 0.f;
        #pragma unroll
        for (int i = 0; i < 8; i++) s += red[i];
        s_rs = rsqrtf(s * (1.f / 1024.f) + 1e-5f);
    }
    __syncthreads();
    const float rs = s_rs;
    float4 gv = ((const float4*)g)[t];
    float4 bv = ((const float4*)be)[t];
    float4 o;
    o.x = dx * rs * gv.x + bv.x;
    o.y = dy * rs * gv.y + bv.y;
    o.z = dz * rs * gv.z + bv.z;
    o.w = dw * rs * gv.w + bv.w;
    ((float4*)(out + row * 1024))[t] = o;
    if (out_r) {
        float4 r;
        r.x = round_tf32(o.x); r.y = round_tf32(o.y);
        r.z = round_tf32(o.z); r.w = round_tf32(o.w);
        ((float4*)(out_r + row * 1024))[t] = r;
    }
}

// ---------------------------------------------------------------------------
// launch
// ---------------------------------------------------------------------------
extern "C" void kernel_launch(void* const* d_in, const int* in_sizes, int n_in,
                              void* d_out, int out_size)
{
    const float* x    = (const float*)d_in[0];
    const float* Wqkv = (const float*)d_in[1];
    const float* bqkv = (const float*)d_in[2];
    const float* Wo   = (const float*)d_in[3];
    const float* bo   = (const float*)d_in[4];
    const float* W1   = (const float*)d_in[5];
    const float* b1   = (const float*)d_in[6];
    const float* W2   = (const float*)d_in[7];
    const float* b2   = (const float*)d_in[8];
    const float* g1   = (const float*)d_in[9];
    const float* be1  = (const float*)d_in[10];
    const float* g2   = (const float*)d_in[11];
    const float* be2  = (const float*)d_in[12];
    float* out = (float*)d_out;

    float *qkv, *ctx, *y, *x1, *x1r, *hb, *xr, *wqkvr, *wor, *w1r, *w2r;
    cudaGetSymbolAddress((void**)&qkv,   g_qkv);
    cudaGetSymbolAddress((void**)&ctx,   g_ctx);
    cudaGetSymbolAddress((void**)&y,     g_y);
    cudaGetSymbolAddress((void**)&x1,    g_x1);
    cudaGetSymbolAddress((void**)&x1r,   g_x1r);
    cudaGetSymbolAddress((void**)&hb,    g_h);
    cudaGetSymbolAddress((void**)&xr,    g_xr);
    cudaGetSymbolAddress((void**)&wqkvr, g_wqkvr);
    cudaGetSymbolAddress((void**)&wor,   g_wor);
    cudaGetSymbolAddress((void**)&w1r,   g_w1r);
    cudaGetSymbolAddress((void**)&w2r,   g_w2r);

    cudaFuncSetAttribute(attn_kernel,
                         cudaFuncAttributeMaxDynamicSharedMemorySize, ATTN_SMEM);
    cudaFuncSetAttribute((tgemm<false, false, false>),
                         cudaFuncAttributeMaxDynamicSharedMemorySize, GEMM_SMEM);
    cudaFuncSetAttribute((tgemm<false, true, false>),
                         cudaFuncAttributeMaxDynamicSharedMemorySize, GEMM_SMEM);
    cudaFuncSetAttribute((tgemm<true, false, true>),
                         cudaFuncAttributeMaxDynamicSharedMemorySize, GEMM_SMEM);

    dim3 thr(256);

    // 0) pre-round GEMM inputs to tf32 bit patterns
    round_kernel<<<(TOKENS * CDIM / 4 + 255) / 256, thr>>>(x, xr, TOKENS * CDIM / 4);
    round_kernel<<<(3 * CDIM * CDIM / 4 + 255) / 256, thr>>>(Wqkv, wqkvr, 3 * CDIM * CDIM / 4);
    round_kernel<<<(CDIM * CDIM / 4 + 255) / 256, thr>>>(Wo, wor, CDIM * CDIM / 4);
    round_kernel<<<(FFDIM * CDIM / 4 + 255) / 256, thr>>>(W1, w1r, FFDIM * CDIM / 4);
    round_kernel<<<(CDIM * FFDIM / 4 + 255) / 256, thr>>>(W2, w2r, CDIM * FFDIM / 4);

    // 1) QKV projection
    tgemm<false, false, false><<<dim3(3072 / GBN, TOKENS / GBM), thr, GEMM_SMEM>>>(
        xr, wqkvr, bqkv, nullptr, qkv, TOKENS, 3 * CDIM, CDIM);
    // 2) banded attention (writes tf32-rounded ctx)
    attn_kernel<<<dim3(1024 / 64, 4 * 16), thr, ATTN_SMEM>>>(qkv, ctx);
    // 3) Wo + bias + residual(x exact)
    tgemm<false, true, false><<<dim3(CDIM / GBN, TOKENS / GBM), thr, GEMM_SMEM>>>(
        ctx, wor, bo, x, y, TOKENS, CDIM, CDIM);
    // 4) LN1 -> x1 (exact) + x1r (rounded)
    ln_kernel<<<TOKENS, thr>>>(y, g1, be1, x1, x1r);
    // 5) W1 + bias + GELU (writes tf32-rounded h)
    tgemm<true, false, true><<<dim3(FFDIM / GBN, TOKENS / GBM), thr, GEMM_SMEM>>>(
        x1r, w1r, b1, nullptr, hb, TOKENS, FFDIM, CDIM);
    // 6) W2 + bias + residual(x1 exact)
    tgemm<false, true, false><<<dim3(CDIM / GBN, TOKENS / GBM), thr, GEMM_SMEM>>>(
        hb, w2r, b2, x1, y, TOKENS, CDIM, FFDIM);
    // 7) LN2 -> out
    ln_kernel<<<TOKENS, thr>>>(y, g2, be2, out, nullptr);
}